// round 1
// baseline (speedup 1.0000x reference)
#include <cuda_runtime.h>
#include <math.h>

// Problem constants
#define T_DIM   64
#define N_NODES 2048
#define C_DIM   64
#define E_EDGES 32768
#define R_DIM   192          // K(3) * CIN(64), flattened reduction dim, r = k*64+ci
#define NODE_TILE 64
#define WPAD    65           // padded weight row stride (conflict-free transpose store)

// ---------------- scratch (device globals: no allocs allowed) ----------------
__device__ float  g_xw[(size_t)T_DIM * N_NODES * C_DIM];   // 33.5 MB: h @ gcn_w
__device__ float  g_deg[N_NODES];
__device__ float  g_dinv[N_NODES];
__device__ float  g_invdeg[N_NODES];
__device__ int    g_cnt[N_NODES];
__device__ int    g_start[N_NODES + 1];
__device__ int    g_cursor[N_NODES];
__device__ int    g_csr_src[E_EDGES];
__device__ float  g_csr_norm[E_EDGES];
__device__ double g_sum[C_DIM];
__device__ double g_sumsq[C_DIM];
__device__ __align__(16) float g_scale[C_DIM];
__device__ __align__(16) float g_shift[C_DIM];

// ---------------- init ----------------
__global__ void k_zero() {
    int i = blockIdx.x * blockDim.x + threadIdx.x;
    if (i < N_NODES) { g_deg[i] = 1.0f; g_cnt[i] = 0; }   // +1 self-loop baked in
    if (i < C_DIM)   { g_sum[i] = 0.0; g_sumsq[i] = 0.0; }
}

// ---------------- degree + in-edge counts ----------------
__global__ void k_deg(const int* __restrict__ ei, const float* __restrict__ ew) {
    int e = blockIdx.x * blockDim.x + threadIdx.x;
    if (e < E_EDGES) {
        int dst = ei[E_EDGES + e];
        atomicAdd(&g_deg[dst], ew[e]);
        atomicAdd(&g_cnt[dst], 1);
    }
}

// ---------------- exclusive scan over 2048 counts (Blelloch, 1 block) --------
__global__ void k_scan() {
    __shared__ int s[2048];
    int tid = threadIdx.x;  // 1024 threads
    s[tid] = g_cnt[tid];
    s[tid + 1024] = g_cnt[tid + 1024];
    int offset = 1;
    for (int d = 1024; d > 0; d >>= 1) {
        __syncthreads();
        if (tid < d) {
            int ai = offset * (2 * tid + 1) - 1;
            int bi = offset * (2 * tid + 2) - 1;
            s[bi] += s[ai];
        }
        offset <<= 1;
    }
    if (tid == 0) s[2047] = 0;
    for (int d = 1; d < 2048; d <<= 1) {
        offset >>= 1;
        __syncthreads();
        if (tid < d) {
            int ai = offset * (2 * tid + 1) - 1;
            int bi = offset * (2 * tid + 2) - 1;
            int tv = s[ai]; s[ai] = s[bi]; s[bi] += tv;
        }
    }
    __syncthreads();
    for (int n = tid; n < 2048; n += 1024) {
        g_start[n]  = s[n];
        g_cursor[n] = s[n];
        float d = g_deg[n];
        g_dinv[n]   = rsqrtf(d);
        g_invdeg[n] = 1.0f / d;
    }
    if (tid == 0) g_start[N_NODES] = E_EDGES;
}

// ---------------- CSR fill (by dst) ----------------
__global__ void k_fill(const int* __restrict__ ei, const float* __restrict__ ew) {
    int e = blockIdx.x * blockDim.x + threadIdx.x;
    if (e < E_EDGES) {
        int src = ei[e];
        int dst = ei[E_EDGES + e];
        int pos = atomicAdd(&g_cursor[dst], 1);
        g_csr_src[pos]  = src;
        g_csr_norm[pos] = g_dinv[src] * ew[e] * g_dinv[dst];
    }
}

// ---------------- fused gated conv + GCN linear ----------------
// Block: (t, 64-node tile), 512 threads. co = tid&63, node-group ng = tid>>6.
// Each thread: 8 nodes x 1 channel for conv/gate, then 8 nodes x 1 channel of xw.
extern __shared__ float sm_conv[];
__global__ void __launch_bounds__(512, 1)
k_conv(const float* __restrict__ x,
       const float* __restrict__ conv_w, const float* __restrict__ conv_b,
       const float* __restrict__ gate_w, const float* __restrict__ gate_b,
       const float* __restrict__ gcn_w) {
    float* swc = sm_conv;                       // [192][65]
    float* swg = swc + R_DIM * WPAD;            // [192][65]
    float* sg  = swg + R_DIM * WPAD;            // [64][64] gcn_w (row-major)
    float* sx  = sg  + C_DIM * C_DIM;           // [64 nodes][192]  (r = k*64+ci)
    float* sh  = sx  + NODE_TILE * R_DIM;       // [64 nodes][64]   gated hidden

    const int tid = threadIdx.x;
    const int t   = blockIdx.y;
    const int n0  = blockIdx.x * NODE_TILE;

    // Transposed weight load: swc[r][co] = conv_w[co][ci][k], r = k*64+ci.
    for (int idx = tid; idx < C_DIM * R_DIM; idx += 512) {
        int cow = idx / R_DIM;
        int rem = idx - cow * R_DIM;   // ci*3 + k
        int ci  = rem / 3;
        int k   = rem - ci * 3;
        int r   = k * C_DIM + ci;
        swc[r * WPAD + cow] = conv_w[idx];
        swg[r * WPAD + cow] = gate_w[idx];
    }
    for (int idx = tid; idx < C_DIM * C_DIM; idx += 512) sg[idx] = gcn_w[idx];

    // x taps for this node tile (t-2, t, t+2), zero-padded in time
    for (int idx = tid; idx < NODE_TILE * R_DIM; idx += 512) {
        int nl  = idx / R_DIM;
        int rem = idx - nl * R_DIM;
        int k   = rem >> 6;
        int ci  = rem & 63;
        int tt  = t + 2 * k - 2;
        sx[idx] = (tt >= 0 && tt < T_DIM)
                    ? x[((size_t)tt * N_NODES + n0 + nl) * C_DIM + ci] : 0.0f;
    }

    const int co = tid & 63;
    const int ng = tid >> 6;          // 0..7
    const float cb = conv_b[co];
    const float gb = gate_b[co];
    __syncthreads();

    float accC[8], accG[8];
#pragma unroll
    for (int i = 0; i < 8; i++) { accC[i] = cb; accG[i] = gb; }

    for (int k = 0; k < 3; k++) {
#pragma unroll
        for (int c4 = 0; c4 < 16; c4++) {
            const int rb = k * 64 + c4 * 4;
            const float wc0 = swc[(rb + 0) * WPAD + co];
            const float wc1 = swc[(rb + 1) * WPAD + co];
            const float wc2 = swc[(rb + 2) * WPAD + co];
            const float wc3 = swc[(rb + 3) * WPAD + co];
            const float wg0 = swg[(rb + 0) * WPAD + co];
            const float wg1 = swg[(rb + 1) * WPAD + co];
            const float wg2 = swg[(rb + 2) * WPAD + co];
            const float wg3 = swg[(rb + 3) * WPAD + co];
#pragma unroll
            for (int i = 0; i < 8; i++) {
                const float4 xv =
                    *reinterpret_cast<const float4*>(&sx[(ng + 8 * i) * R_DIM + rb]);
                accC[i] = fmaf(wc0, xv.x, accC[i]);
                accC[i] = fmaf(wc1, xv.y, accC[i]);
                accC[i] = fmaf(wc2, xv.z, accC[i]);
                accC[i] = fmaf(wc3, xv.w, accC[i]);
                accG[i] = fmaf(wg0, xv.x, accG[i]);
                accG[i] = fmaf(wg1, xv.y, accG[i]);
                accG[i] = fmaf(wg2, xv.z, accG[i]);
                accG[i] = fmaf(wg3, xv.w, accG[i]);
            }
        }
    }

    // gate + store hidden tile
#pragma unroll
    for (int i = 0; i < 8; i++) {
        float sgm = 1.0f / (1.0f + __expf(-accG[i]));
        sh[(ng + 8 * i) * C_DIM + co] = accC[i] * sgm;
    }
    __syncthreads();

    // xw = h @ gcn_w (64x64)
    float accO[8];
#pragma unroll
    for (int i = 0; i < 8; i++) accO[i] = 0.0f;
#pragma unroll
    for (int c4 = 0; c4 < 16; c4++) {
        const float g0 = sg[(c4 * 4 + 0) * C_DIM + co];
        const float g1 = sg[(c4 * 4 + 1) * C_DIM + co];
        const float g2 = sg[(c4 * 4 + 2) * C_DIM + co];
        const float g3 = sg[(c4 * 4 + 3) * C_DIM + co];
#pragma unroll
        for (int i = 0; i < 8; i++) {
            const float4 hv =
                *reinterpret_cast<const float4*>(&sh[(ng + 8 * i) * C_DIM + c4 * 4]);
            accO[i] = fmaf(g0, hv.x, accO[i]);
            accO[i] = fmaf(g1, hv.y, accO[i]);
            accO[i] = fmaf(g2, hv.z, accO[i]);
            accO[i] = fmaf(g3, hv.w, accO[i]);
        }
    }
#pragma unroll
    for (int i = 0; i < 8; i++)
        g_xw[((size_t)t * N_NODES + n0 + ng + 8 * i) * C_DIM + co] = accO[i];
}

// ---------------- per-dst gather (no atomics on hot path) + BN stats --------
__global__ void k_gather(float* __restrict__ out, const float* __restrict__ gcn_b) {
    __shared__ double ssum[C_DIM], ssq[C_DIM];
    const int tid = threadIdx.x;
    if (tid < C_DIM) { ssum[tid] = 0.0; ssq[tid] = 0.0; }
    __syncthreads();

    const int lane = tid & 31;
    const int warp = tid >> 5;
    const int wg   = blockIdx.x * 8 + warp;   // 16384 warps total, 8 rows each

    const float b0 = gcn_b[lane];
    const float b1 = gcn_b[lane + 32];
    double ls0 = 0.0, ls1 = 0.0, lq0 = 0.0, lq1 = 0.0;

    for (int i = 0; i < 8; i++) {
        const int p = wg * 8 + i;             // p == t*2048 + n
        const int t = p >> 11;
        const int n = p & 2047;
        const float* row = g_xw + (size_t)p * 64;
        const float inv = g_invdeg[n];
        float a0 = row[lane]      * inv + b0;
        float a1 = row[lane + 32] * inv + b1;
        const int s0 = g_start[n], s1 = g_start[n + 1];
        for (int j = s0; j < s1; j++) {
            const int   src = g_csr_src[j];
            const float nm  = g_csr_norm[j];
            const float* sr = g_xw + ((size_t)t * 2048 + src) * 64;
            a0 = fmaf(nm, sr[lane],      a0);
            a1 = fmaf(nm, sr[lane + 32], a1);
        }
        out[(size_t)p * 64 + lane]      = a0;
        out[(size_t)p * 64 + lane + 32] = a1;
        ls0 += a0; lq0 += (double)a0 * a0;
        ls1 += a1; lq1 += (double)a1 * a1;
    }
    atomicAdd(&ssum[lane],      ls0); atomicAdd(&ssq[lane],      lq0);
    atomicAdd(&ssum[lane + 32], ls1); atomicAdd(&ssq[lane + 32], lq1);
    __syncthreads();
    if (tid < C_DIM) {
        atomicAdd(&g_sum[tid],   ssum[tid]);
        atomicAdd(&g_sumsq[tid], ssq[tid]);
    }
}

// ---------------- BN stats -> per-channel scale/shift ----------------
__global__ void k_stats(const float* __restrict__ gamma, const float* __restrict__ beta) {
    int c = threadIdx.x;
    if (c < C_DIM) {
        const double M = (double)T_DIM * N_NODES;   // 131072
        double m   = g_sum[c] / M;
        double var = g_sumsq[c] / M - m * m;
        float sc = (float)(1.0 / sqrt(var + 1e-5)) * gamma[c];
        g_scale[c] = sc;
        g_shift[c] = beta[c] - (float)m * sc;
    }
}

// ---------------- BN apply + ReLU (in place on d_out) ----------------
__global__ void k_apply(float* __restrict__ out) {
    const int idx = blockIdx.x * blockDim.x + threadIdx.x;   // float4 granularity
    const int c4  = idx & 15;
    float4 v  = reinterpret_cast<float4*>(out)[idx];
    const float4 sc = reinterpret_cast<const float4*>(g_scale)[c4];
    const float4 sh = reinterpret_cast<const float4*>(g_shift)[c4];
    v.x = fmaxf(fmaf(v.x, sc.x, sh.x), 0.0f);
    v.y = fmaxf(fmaf(v.y, sc.y, sh.y), 0.0f);
    v.z = fmaxf(fmaf(v.z, sc.z, sh.z), 0.0f);
    v.w = fmaxf(fmaf(v.w, sc.w, sh.w), 0.0f);
    reinterpret_cast<float4*>(out)[idx] = v;
}

// ---------------- launch ----------------
extern "C" void kernel_launch(void* const* d_in, const int* in_sizes, int n_in,
                              void* d_out, int out_size) {
    const float* x      = (const float*)d_in[0];
    const int*   ei     = (const int*)  d_in[1];
    const float* ew     = (const float*)d_in[2];
    const float* conv_w = (const float*)d_in[3];
    const float* conv_b = (const float*)d_in[4];
    const float* gate_w = (const float*)d_in[5];
    const float* gate_b = (const float*)d_in[6];
    const float* gcn_w  = (const float*)d_in[7];
    const float* gcn_b  = (const float*)d_in[8];
    const float* bn_g   = (const float*)d_in[9];
    const float* bn_b   = (const float*)d_in[10];
    float* out = (float*)d_out;

    k_zero<<<8, 256>>>();
    k_deg <<<E_EDGES / 256, 256>>>(ei, ew);
    k_scan<<<1, 1024>>>();
    k_fill<<<E_EDGES / 256, 256>>>(ei, ew);

    const size_t smem =
        (size_t)(2 * R_DIM * WPAD + C_DIM * C_DIM + NODE_TILE * R_DIM +
                 NODE_TILE * C_DIM) * sizeof(float);   // ~177.5 KB
    cudaFuncSetAttribute(k_conv, cudaFuncAttributeMaxDynamicSharedMemorySize,
                         (int)smem);
    dim3 gridc(N_NODES / NODE_TILE, T_DIM);
    k_conv<<<gridc, 512, smem>>>(x, conv_w, conv_b, gate_w, gate_b, gcn_w);

    k_gather<<<(T_DIM * N_NODES) / (8 * 8), 256>>>(out, gcn_b);  // 2048 blocks
    k_stats <<<1, 64>>>(bn_g, bn_b);
    k_apply <<<(T_DIM * N_NODES * C_DIM) / 4 / 256, 256>>>(out); // 8192 blocks
}

// round 3
// speedup vs baseline: 1.6015x; 1.6015x over previous
#include <cuda_runtime.h>
#include <cuda_bf16.h>
#include <cstdint>
#include <math.h>

// Problem constants
#define T_DIM   64
#define N_NODES 2048
#define C_DIM   64
#define E_EDGES 32768
#define NUM_TILES 1024              // 64 t * 16 node tiles of 128

#define AST 200   // A/B smem row stride in bf16 halves (conflict-free: 100 words)
#define GST 72    // g2 smem row stride in halves (36 words)

// ---------------- scratch (device globals: no allocs allowed) ----------------
__device__ __align__(16) float          g_xw[(size_t)T_DIM * N_NODES * C_DIM];
__device__ __align__(16) __nv_bfloat16  g_xhi[(size_t)T_DIM * N_NODES * C_DIM];
__device__ __align__(16) __nv_bfloat16  g_xlo[(size_t)T_DIM * N_NODES * C_DIM];
__device__ __align__(16) __nv_bfloat16  g_wB_hi[128 * 192];   // [co2][tap*64+ci]
__device__ __align__(16) __nv_bfloat16  g_wB_lo[128 * 192];
__device__ __align__(16) __nv_bfloat16  g_g2_hi[64 * 64];     // [co][ci] = gcn_w[ci][co]
__device__ __align__(16) __nv_bfloat16  g_g2_lo[64 * 64];
__device__ float  g_deg[N_NODES];
__device__ float  g_dinv[N_NODES];
__device__ float  g_invdeg[N_NODES];
__device__ int    g_cnt[N_NODES];
__device__ int    g_start[N_NODES + 1];
__device__ int    g_cursor[N_NODES];
__device__ int    g_csr_src[E_EDGES];
__device__ float  g_csr_norm[E_EDGES];
__device__ double g_sum[C_DIM];
__device__ double g_sumsq[C_DIM];
__device__ __align__(16) float g_scale[C_DIM];
__device__ __align__(16) float g_shift[C_DIM];

// ---------------- mma.sync bf16 (sm_80+, works at compute_100) --------------
__device__ __forceinline__ void mma_bf16(float* d, const uint32_t* a,
                                         const uint32_t* b) {
    asm volatile(
        "mma.sync.aligned.m16n8k16.row.col.f32.bf16.bf16.f32 "
        "{%0,%1,%2,%3}, {%4,%5,%6,%7}, {%8,%9}, {%0,%1,%2,%3};"
        : "+f"(d[0]), "+f"(d[1]), "+f"(d[2]), "+f"(d[3])
        : "r"(a[0]), "r"(a[1]), "r"(a[2]), "r"(a[3]), "r"(b[0]), "r"(b[1]));
}

// ======================= graph-prep kernels ==================================
__global__ void k_zero() {
    int i = blockIdx.x * blockDim.x + threadIdx.x;
    if (i < N_NODES) { g_deg[i] = 1.0f; g_cnt[i] = 0; }
    if (i < C_DIM)   { g_sum[i] = 0.0; g_sumsq[i] = 0.0; }
}
__global__ void k_deg(const int* __restrict__ ei, const float* __restrict__ ew) {
    int e = blockIdx.x * blockDim.x + threadIdx.x;
    if (e < E_EDGES) {
        int dst = ei[E_EDGES + e];
        atomicAdd(&g_deg[dst], ew[e]);
        atomicAdd(&g_cnt[dst], 1);
    }
}
__global__ void k_scan() {
    __shared__ int s[2048];
    int tid = threadIdx.x;
    s[tid] = g_cnt[tid];
    s[tid + 1024] = g_cnt[tid + 1024];
    int offset = 1;
    for (int d = 1024; d > 0; d >>= 1) {
        __syncthreads();
        if (tid < d) {
            int ai = offset * (2 * tid + 1) - 1, bi = offset * (2 * tid + 2) - 1;
            s[bi] += s[ai];
        }
        offset <<= 1;
    }
    if (tid == 0) s[2047] = 0;
    for (int d = 1; d < 2048; d <<= 1) {
        offset >>= 1;
        __syncthreads();
        if (tid < d) {
            int ai = offset * (2 * tid + 1) - 1, bi = offset * (2 * tid + 2) - 1;
            int tv = s[ai]; s[ai] = s[bi]; s[bi] += tv;
        }
    }
    __syncthreads();
    for (int n = tid; n < 2048; n += 1024) {
        g_start[n] = s[n]; g_cursor[n] = s[n];
        float d = g_deg[n];
        g_dinv[n] = rsqrtf(d);
        g_invdeg[n] = 1.0f / d;
    }
    if (tid == 0) g_start[N_NODES] = E_EDGES;
}
__global__ void k_fill(const int* __restrict__ ei, const float* __restrict__ ew) {
    int e = blockIdx.x * blockDim.x + threadIdx.x;
    if (e < E_EDGES) {
        int src = ei[e], dst = ei[E_EDGES + e];
        int pos = atomicAdd(&g_cursor[dst], 1);
        g_csr_src[pos] = src;
        g_csr_norm[pos] = g_dinv[src] * ew[e] * g_dinv[dst];
    }
}

// ================= x -> bf16 hi/lo (plain layout) ============================
__global__ void k_prep_x(const float* __restrict__ x) {
    const int idx = blockIdx.x * blockDim.x + threadIdx.x;
    const float v = x[idx];
    __nv_bfloat16 hi = __float2bfloat16(v);
    __nv_bfloat16 lo = __float2bfloat16(v - __bfloat162float(hi));
    g_xhi[idx] = hi;
    g_xlo[idx] = lo;
}

// ================= weights -> bf16 hi/lo =====================================
__global__ void k_prep_w(const float* __restrict__ conv_w, const float* __restrict__ gate_w,
                         const float* __restrict__ gcn_w) {
    const int tid = threadIdx.x;
    // wB[co2][tap*64+ci]: co2<64 -> conv_w[co2][ci][tap], else gate_w
    for (int i = tid; i < 128 * 192; i += blockDim.x) {
        const int co2 = i / 192;
        const int kf  = i - co2 * 192;
        const int tap = kf >> 6;
        const int ci  = kf & 63;
        const float v = (co2 < 64) ? conv_w[co2 * 192 + ci * 3 + tap]
                                   : gate_w[(co2 - 64) * 192 + ci * 3 + tap];
        __nv_bfloat16 hi = __float2bfloat16(v);
        __nv_bfloat16 lo = __float2bfloat16(v - __bfloat162float(hi));
        g_wB_hi[i] = hi;
        g_wB_lo[i] = lo;
    }
    // g2[co][ci] = gcn_w[ci][co]
    for (int i = tid; i < 64 * 64; i += blockDim.x) {
        const int co = i >> 6, ci = i & 63;
        const float v = gcn_w[ci * 64 + co];
        __nv_bfloat16 hi = __float2bfloat16(v);
        __nv_bfloat16 lo = __float2bfloat16(v - __bfloat162float(hi));
        g_g2_hi[i] = hi;
        g_g2_lo[i] = lo;
    }
}

// =============== mma.sync fused gated conv + GCN linear ======================
// smem (halves): B hi/lo [128][AST], g2 hi/lo [64][GST], A hi/lo [128][AST],
// then fp32 biases. Total 223744 B.
static constexpr int SMEM_NEED =
    (4 * 128 * AST + 2 * 64 * GST) * 2 + 2 * 64 * 4;

__global__ void __launch_bounds__(256, 1)
k_mma(const float* __restrict__ conv_b, const float* __restrict__ gate_b) {
    extern __shared__ __nv_bfloat16 sm[];
    __nv_bfloat16* sBhi  = sm;
    __nv_bfloat16* sBlo  = sBhi + 128 * AST;
    __nv_bfloat16* sG2hi = sBlo + 128 * AST;
    __nv_bfloat16* sG2lo = sG2hi + 64 * GST;
    __nv_bfloat16* sAhi  = sG2lo + 64 * GST;
    __nv_bfloat16* sAlo  = sAhi + 128 * AST;
    float* s_cb = (float*)(sAlo + 128 * AST);
    float* s_gb = s_cb + 64;

    const int tid  = threadIdx.x;
    const int wid  = tid >> 5;
    const int lane = tid & 31;
    const int qid  = lane >> 2;      // l/4
    const int tp   = lane & 3;       // l%4
    const int cp   = tp * 2;
    const int wm   = wid & 3;        // m quadrant (32 rows)
    const int wn   = wid >> 2;       // n half
    const int rbase = wm * 32 + qid;

    // ---- one-time staging: weights, g2, biases ----
    for (int i = tid; i < 128 * 24; i += 256) {          // 24 uint4 per row
        const int n = i / 24, ch = i - n * 24;
        ((uint4*)(sBhi + n * AST))[ch] = ((const uint4*)(g_wB_hi + n * 192))[ch];
        ((uint4*)(sBlo + n * AST))[ch] = ((const uint4*)(g_wB_lo + n * 192))[ch];
    }
    for (int i = tid; i < 64 * 8; i += 256) {            // 8 uint4 per row
        const int n = i >> 3, ch = i & 7;
        ((uint4*)(sG2hi + n * GST))[ch] = ((const uint4*)(g_g2_hi + n * 64))[ch];
        ((uint4*)(sG2lo + n * GST))[ch] = ((const uint4*)(g_g2_lo + n * 64))[ch];
    }
    if (tid < 64) { s_cb[tid] = conv_b[tid]; s_gb[tid] = gate_b[tid]; }
    __syncthreads();

    for (int p = blockIdx.x; p < NUM_TILES; p += gridDim.x) {
        const int t  = p >> 4;
        const int n0 = (p & 15) << 7;

        // ---- stage A tile: 3 taps x hi/lo, zero-padded in time ----
        for (int tap = 0; tap < 3; tap++) {
            const int tt = t + 2 * tap - 2;
            const bool ok = (tt >= 0 && tt < T_DIM);
            const uint4* shi = (const uint4*)(g_xhi + ((size_t)tt * N_NODES + n0) * 64);
            const uint4* slo = (const uint4*)(g_xlo + ((size_t)tt * N_NODES + n0) * 64);
            const uint4 z = make_uint4(0, 0, 0, 0);
            for (int i = tid; i < 1024; i += 256) {      // 128 rows x 8 uint4
                const int n = i >> 3, ch = i & 7;
                ((uint4*)(sAhi + n * AST + tap * 64))[ch] = ok ? shi[i] : z;
                ((uint4*)(sAlo + n * AST + tap * 64))[ch] = ok ? slo[i] : z;
            }
        }
        __syncthreads();

        // ---- MMA1: D1[128,128] = A[128,192] . B^T, hi/lo 3 combos ----
        float acc[2][8][4];
#pragma unroll
        for (int mb = 0; mb < 2; mb++)
#pragma unroll
            for (int j = 0; j < 8; j++)
#pragma unroll
                for (int r = 0; r < 4; r++) acc[mb][j][r] = 0.0f;

        for (int combo = 0; combo < 3; combo++) {
            const __nv_bfloat16* Ab = (combo == 2) ? sAlo : sAhi;
            const __nv_bfloat16* Bb = (combo == 1) ? sBlo : sBhi;
            for (int ks = 0; ks < 12; ks++) {
                const int k0 = ks * 16 + cp;
                uint32_t a[2][4];
#pragma unroll
                for (int mb = 0; mb < 2; mb++) {
                    const __nv_bfloat16* ap = Ab + (rbase + mb * 16) * AST + k0;
                    a[mb][0] = *(const uint32_t*)ap;
                    a[mb][1] = *(const uint32_t*)(ap + 8 * AST);
                    a[mb][2] = *(const uint32_t*)(ap + 8);
                    a[mb][3] = *(const uint32_t*)(ap + 8 * AST + 8);
                }
#pragma unroll
                for (int jj = 0; jj < 8; jj++) {
                    const int nbg = (jj < 4) ? (wn * 4 + jj) : (8 + wn * 4 + jj - 4);
                    const __nv_bfloat16* bp = Bb + (nbg * 8 + qid) * AST + k0;
                    uint32_t b[2];
                    b[0] = *(const uint32_t*)bp;
                    b[1] = *(const uint32_t*)(bp + 8);
                    mma_bf16(acc[0][jj], a[0], b);
                    mma_bf16(acc[1][jj], a[1], b);
                }
            }
        }
        __syncthreads();   // all warps done reading A before h overwrites it

        // ---- epilogue1: h = (conv+cb)*sigmoid(gate+gb) -> bf16 hi/lo smem ---
#pragma unroll
        for (int mb = 0; mb < 2; mb++) {
#pragma unroll
            for (int jj = 0; jj < 4; jj++) {
                const float* ac = acc[mb][jj];
                const float* ag = acc[mb][jj + 4];
                const int c0 = wn * 32 + jj * 8 + cp;
                const int r0 = rbase + mb * 16;
                const float cb0 = s_cb[c0], cb1 = s_cb[c0 + 1];
                const float gb0 = s_gb[c0], gb1 = s_gb[c0 + 1];
                float h00 = (ac[0] + cb0) * (1.0f / (1.0f + __expf(-(ag[0] + gb0))));
                float h01 = (ac[1] + cb1) * (1.0f / (1.0f + __expf(-(ag[1] + gb1))));
                float h10 = (ac[2] + cb0) * (1.0f / (1.0f + __expf(-(ag[2] + gb0))));
                float h11 = (ac[3] + cb1) * (1.0f / (1.0f + __expf(-(ag[3] + gb1))));
                __nv_bfloat16 h00h = __float2bfloat16(h00);
                __nv_bfloat16 h01h = __float2bfloat16(h01);
                __nv_bfloat16 h10h = __float2bfloat16(h10);
                __nv_bfloat16 h11h = __float2bfloat16(h11);
                __nv_bfloat16 h00l = __float2bfloat16(h00 - __bfloat162float(h00h));
                __nv_bfloat16 h01l = __float2bfloat16(h01 - __bfloat162float(h01h));
                __nv_bfloat16 h10l = __float2bfloat16(h10 - __bfloat162float(h10h));
                __nv_bfloat16 h11l = __float2bfloat16(h11 - __bfloat162float(h11h));
                *(uint32_t*)(sAhi + r0 * AST + c0) =
                    ((uint32_t)__bfloat16_as_ushort(h01h) << 16) | __bfloat16_as_ushort(h00h);
                *(uint32_t*)(sAhi + (r0 + 8) * AST + c0) =
                    ((uint32_t)__bfloat16_as_ushort(h11h) << 16) | __bfloat16_as_ushort(h10h);
                *(uint32_t*)(sAlo + r0 * AST + c0) =
                    ((uint32_t)__bfloat16_as_ushort(h01l) << 16) | __bfloat16_as_ushort(h00l);
                *(uint32_t*)(sAlo + (r0 + 8) * AST + c0) =
                    ((uint32_t)__bfloat16_as_ushort(h11l) << 16) | __bfloat16_as_ushort(h10l);
            }
        }
        __syncthreads();

        // ---- MMA2: D2[128,64] = h[128,64] . g2^T, hi/lo 3 combos ----
        float acc2[2][4][4];
#pragma unroll
        for (int mb = 0; mb < 2; mb++)
#pragma unroll
            for (int j = 0; j < 4; j++)
#pragma unroll
                for (int r = 0; r < 4; r++) acc2[mb][j][r] = 0.0f;

        for (int combo = 0; combo < 3; combo++) {
            const __nv_bfloat16* Ab = (combo == 2) ? sAlo : sAhi;
            const __nv_bfloat16* Bb = (combo == 1) ? sG2lo : sG2hi;
#pragma unroll
            for (int ks = 0; ks < 4; ks++) {
                const int k0 = ks * 16 + cp;
                uint32_t a[2][4];
#pragma unroll
                for (int mb = 0; mb < 2; mb++) {
                    const __nv_bfloat16* ap = Ab + (rbase + mb * 16) * AST + k0;
                    a[mb][0] = *(const uint32_t*)ap;
                    a[mb][1] = *(const uint32_t*)(ap + 8 * AST);
                    a[mb][2] = *(const uint32_t*)(ap + 8);
                    a[mb][3] = *(const uint32_t*)(ap + 8 * AST + 8);
                }
#pragma unroll
                for (int jj = 0; jj < 4; jj++) {
                    const __nv_bfloat16* bp = Bb + ((wn * 4 + jj) * 8 + qid) * GST + k0;
                    uint32_t b[2];
                    b[0] = *(const uint32_t*)bp;
                    b[1] = *(const uint32_t*)(bp + 8);
                    mma_bf16(acc2[0][jj], a[0], b);
                    mma_bf16(acc2[1][jj], a[1], b);
                }
            }
        }

        // ---- epilogue2: write xw tile ----
        float* obase = g_xw + ((size_t)t * N_NODES + n0) * 64;
#pragma unroll
        for (int mb = 0; mb < 2; mb++) {
#pragma unroll
            for (int jj = 0; jj < 4; jj++) {
                const int c0 = wn * 32 + jj * 8 + cp;
                const int r0 = rbase + mb * 16;
                *(float2*)(obase + r0 * 64 + c0) =
                    make_float2(acc2[mb][jj][0], acc2[mb][jj][1]);
                *(float2*)(obase + (r0 + 8) * 64 + c0) =
                    make_float2(acc2[mb][jj][2], acc2[mb][jj][3]);
            }
        }
        __syncthreads();   // protect sA reuse next iteration
    }
}

// ---------------- per-dst gather (no atomics on hot path) + BN stats --------
__global__ void k_gather(float* __restrict__ out, const float* __restrict__ gcn_b) {
    __shared__ double ssum[C_DIM], ssq[C_DIM];
    const int tid = threadIdx.x;
    if (tid < C_DIM) { ssum[tid] = 0.0; ssq[tid] = 0.0; }
    __syncthreads();

    const int lane = tid & 31;
    const int warp = tid >> 5;
    const int wg   = blockIdx.x * 8 + warp;

    const float b0 = gcn_b[lane];
    const float b1 = gcn_b[lane + 32];
    double ls0 = 0.0, ls1 = 0.0, lq0 = 0.0, lq1 = 0.0;

    for (int i = 0; i < 8; i++) {
        const int p = wg * 8 + i;
        const int t = p >> 11;
        const int n = p & 2047;
        const float* row = g_xw + (size_t)p * 64;
        const float inv = g_invdeg[n];
        float a0 = row[lane]      * inv + b0;
        float a1 = row[lane + 32] * inv + b1;
        const int s0 = g_start[n], s1 = g_start[n + 1];
        for (int j = s0; j < s1; j++) {
            const int   src = g_csr_src[j];
            const float nm  = g_csr_norm[j];
            const float* sr = g_xw + ((size_t)t * 2048 + src) * 64;
            a0 = fmaf(nm, sr[lane],      a0);
            a1 = fmaf(nm, sr[lane + 32], a1);
        }
        out[(size_t)p * 64 + lane]      = a0;
        out[(size_t)p * 64 + lane + 32] = a1;
        ls0 += a0; lq0 += (double)a0 * a0;
        ls1 += a1; lq1 += (double)a1 * a1;
    }
    atomicAdd(&ssum[lane],      ls0); atomicAdd(&ssq[lane],      lq0);
    atomicAdd(&ssum[lane + 32], ls1); atomicAdd(&ssq[lane + 32], lq1);
    __syncthreads();
    if (tid < C_DIM) {
        atomicAdd(&g_sum[tid],   ssum[tid]);
        atomicAdd(&g_sumsq[tid], ssq[tid]);
    }
}

__global__ void k_stats(const float* __restrict__ gamma, const float* __restrict__ beta) {
    int c = threadIdx.x;
    if (c < C_DIM) {
        const double M = (double)T_DIM * N_NODES;
        double m   = g_sum[c] / M;
        double var = g_sumsq[c] / M - m * m;
        float sc = (float)(1.0 / sqrt(var + 1e-5)) * gamma[c];
        g_scale[c] = sc;
        g_shift[c] = beta[c] - (float)m * sc;
    }
}

__global__ void k_apply(float* __restrict__ out) {
    const int idx = blockIdx.x * blockDim.x + threadIdx.x;
    const int c4  = idx & 15;
    float4 v  = reinterpret_cast<float4*>(out)[idx];
    const float4 sc = reinterpret_cast<const float4*>(g_scale)[c4];
    const float4 sh = reinterpret_cast<const float4*>(g_shift)[c4];
    v.x = fmaxf(fmaf(v.x, sc.x, sh.x), 0.0f);
    v.y = fmaxf(fmaf(v.y, sc.y, sh.y), 0.0f);
    v.z = fmaxf(fmaf(v.z, sc.z, sh.z), 0.0f);
    v.w = fmaxf(fmaf(v.w, sc.w, sh.w), 0.0f);
    reinterpret_cast<float4*>(out)[idx] = v;
}

// ---------------- launch ----------------
extern "C" void kernel_launch(void* const* d_in, const int* in_sizes, int n_in,
                              void* d_out, int out_size) {
    const float* x      = (const float*)d_in[0];
    const int*   ei     = (const int*)  d_in[1];
    const float* ew     = (const float*)d_in[2];
    const float* conv_w = (const float*)d_in[3];
    const float* conv_b = (const float*)d_in[4];
    const float* gate_w = (const float*)d_in[5];
    const float* gate_b = (const float*)d_in[6];
    const float* gcn_w  = (const float*)d_in[7];
    const float* gcn_b  = (const float*)d_in[8];
    const float* bn_g   = (const float*)d_in[9];
    const float* bn_b   = (const float*)d_in[10];
    float* out = (float*)d_out;

    k_zero  <<<8, 256>>>();
    k_deg   <<<E_EDGES / 256, 256>>>(ei, ew);
    k_prep_x<<<(T_DIM * N_NODES * C_DIM) / 1024, 1024>>>(x);
    k_prep_w<<<1, 512>>>(conv_w, gate_w, gcn_w);
    k_scan  <<<1, 1024>>>();
    k_fill  <<<E_EDGES / 256, 256>>>(ei, ew);

    cudaFuncSetAttribute(k_mma, cudaFuncAttributeMaxDynamicSharedMemorySize,
                         SMEM_NEED);
    k_mma<<<148, 256, SMEM_NEED>>>(conv_b, gate_b);

    k_gather<<<(T_DIM * N_NODES) / (8 * 8), 256>>>(out, gcn_b);
    k_stats <<<1, 64>>>(bn_g, bn_b);
    k_apply <<<(T_DIM * N_NODES * C_DIM) / 4 / 256, 256>>>(out);
}

// round 5
// speedup vs baseline: 1.8883x; 1.1791x over previous
#include <cuda_runtime.h>
#include <cuda_bf16.h>
#include <cstdint>
#include <math.h>

// Problem constants
#define T_DIM   64
#define N_NODES 2048
#define C_DIM   64
#define E_EDGES 32768
#define NUM_TILES 1024              // 64 t * 16 node tiles of 128

#define AST 200   // A/B smem row stride in bf16 halves (conflict-free: 100 words)
#define GST 72    // g2 smem row stride in halves (36 words)

// ---------------- scratch (device globals: no allocs allowed) ----------------
__device__ __align__(16) float          g_xw[(size_t)T_DIM * N_NODES * C_DIM];
__device__ __align__(16) __nv_bfloat16  g_wB_hi[128 * 192];   // [co2][tap*64+ci]
__device__ __align__(16) __nv_bfloat16  g_wB_lo[128 * 192];
__device__ __align__(16) __nv_bfloat16  g_g2_hi[64 * 64];     // [co][ci] = gcn_w[ci][co]
__device__ __align__(16) __nv_bfloat16  g_g2_lo[64 * 64];
__device__ float  g_deg[N_NODES];
__device__ float  g_dinv[N_NODES];
__device__ float  g_invdeg[N_NODES];
__device__ int    g_cnt[N_NODES];
__device__ int    g_start[N_NODES + 1];
__device__ int    g_cursor[N_NODES];
__device__ int    g_csr_src[E_EDGES];
__device__ float  g_csr_norm[E_EDGES];
__device__ double g_sum[C_DIM];
__device__ double g_sumsq[C_DIM];
__device__ __align__(16) float g_scale[C_DIM];
__device__ __align__(16) float g_shift[C_DIM];

// ---------------- mma.sync bf16 -----------------------------------------------
__device__ __forceinline__ void mma_bf16(float* d, const uint32_t* a,
                                         const uint32_t* b) {
    asm volatile(
        "mma.sync.aligned.m16n8k16.row.col.f32.bf16.bf16.f32 "
        "{%0,%1,%2,%3}, {%4,%5,%6,%7}, {%8,%9}, {%0,%1,%2,%3};"
        : "+f"(d[0]), "+f"(d[1]), "+f"(d[2]), "+f"(d[3])
        : "r"(a[0]), "r"(a[1]), "r"(a[2]), "r"(a[3]), "r"(b[0]), "r"(b[1]));
}
__device__ __forceinline__ uint32_t pack2(__nv_bfloat16 a, __nv_bfloat16 b) {
    return ((uint32_t)__bfloat16_as_ushort(b) << 16) | __bfloat16_as_ushort(a);
}

// ======================= graph-prep kernels ==================================
__global__ void k_zero() {
    int i = blockIdx.x * blockDim.x + threadIdx.x;
    if (i < N_NODES) { g_deg[i] = 1.0f; g_cnt[i] = 0; }
    if (i < C_DIM)   { g_sum[i] = 0.0; g_sumsq[i] = 0.0; }
}
__global__ void k_deg(const int* __restrict__ ei, const float* __restrict__ ew) {
    int e = blockIdx.x * blockDim.x + threadIdx.x;
    if (e < E_EDGES) {
        int dst = ei[E_EDGES + e];
        atomicAdd(&g_deg[dst], ew[e]);
        atomicAdd(&g_cnt[dst], 1);
    }
}
__global__ void k_scan() {
    __shared__ int s[2048];
    int tid = threadIdx.x;
    s[tid] = g_cnt[tid];
    s[tid + 1024] = g_cnt[tid + 1024];
    int offset = 1;
    for (int d = 1024; d > 0; d >>= 1) {
        __syncthreads();
        if (tid < d) {
            int ai = offset * (2 * tid + 1) - 1, bi = offset * (2 * tid + 2) - 1;
            s[bi] += s[ai];
        }
        offset <<= 1;
    }
    if (tid == 0) s[2047] = 0;
    for (int d = 1; d < 2048; d <<= 1) {
        offset >>= 1;
        __syncthreads();
        if (tid < d) {
            int ai = offset * (2 * tid + 1) - 1, bi = offset * (2 * tid + 2) - 1;
            int tv = s[ai]; s[ai] = s[bi]; s[bi] += tv;
        }
    }
    __syncthreads();
    for (int n = tid; n < 2048; n += 1024) {
        g_start[n] = s[n]; g_cursor[n] = s[n];
        float d = g_deg[n];
        g_dinv[n] = rsqrtf(d);
        g_invdeg[n] = 1.0f / d;
    }
    if (tid == 0) g_start[N_NODES] = E_EDGES;
}
__global__ void k_fill(const int* __restrict__ ei, const float* __restrict__ ew) {
    int e = blockIdx.x * blockDim.x + threadIdx.x;
    if (e < E_EDGES) {
        int src = ei[e], dst = ei[E_EDGES + e];
        int pos = atomicAdd(&g_cursor[dst], 1);
        g_csr_src[pos] = src;
        g_csr_norm[pos] = g_dinv[src] * ew[e] * g_dinv[dst];
    }
}

// ================= weights -> bf16 hi/lo (grid-parallel) =====================
__global__ void k_prep_w(const float* __restrict__ conv_w, const float* __restrict__ gate_w,
                         const float* __restrict__ gcn_w) {
    const int i = blockIdx.x * blockDim.x + threadIdx.x;   // 0..24575
    if (i < 128 * 192) {
        const int co2 = i / 192;
        const int kf  = i - co2 * 192;
        const int tap = kf >> 6;
        const int ci  = kf & 63;
        const float v = (co2 < 64) ? conv_w[co2 * 192 + ci * 3 + tap]
                                   : gate_w[(co2 - 64) * 192 + ci * 3 + tap];
        __nv_bfloat16 hi = __float2bfloat16(v);
        g_wB_hi[i] = hi;
        g_wB_lo[i] = __float2bfloat16(v - __bfloat162float(hi));
    }
    if (i < 64 * 64) {
        const int co = i >> 6, ci = i & 63;
        const float v = gcn_w[ci * 64 + co];
        __nv_bfloat16 hi = __float2bfloat16(v);
        g_g2_hi[i] = hi;
        g_g2_lo[i] = __float2bfloat16(v - __bfloat162float(hi));
    }
}

// =============== mma.sync fused gated conv + GCN linear ======================
static constexpr int SMEM_NEED =
    (4 * 128 * AST + 2 * 64 * GST) * 2 + 2 * 64 * 4;

__global__ void __launch_bounds__(256, 1)
k_mma(const float* __restrict__ x,
      const float* __restrict__ conv_b, const float* __restrict__ gate_b) {
    extern __shared__ __nv_bfloat16 sm[];
    __nv_bfloat16* sBhi  = sm;
    __nv_bfloat16* sBlo  = sBhi + 128 * AST;
    __nv_bfloat16* sG2hi = sBlo + 128 * AST;
    __nv_bfloat16* sG2lo = sG2hi + 64 * GST;
    __nv_bfloat16* sAhi  = sG2lo + 64 * GST;
    __nv_bfloat16* sAlo  = sAhi + 128 * AST;
    float* s_cb = (float*)(sAlo + 128 * AST);
    float* s_gb = s_cb + 64;

    const int tid  = threadIdx.x;
    const int lane = tid & 31;
    const int wid  = tid >> 5;
    const int qid  = lane >> 2;
    const int tp   = lane & 3;
    const int cp   = tp * 2;
    const int wm   = wid & 3;
    const int wn   = wid >> 2;
    const int rbase = wm * 32 + qid;

    // ---- one-time staging: weights, g2, biases ----
    for (int i = tid; i < 128 * 24; i += 256) {
        const int n = i / 24, ch = i - n * 24;
        ((uint4*)(sBhi + n * AST))[ch] = ((const uint4*)(g_wB_hi + n * 192))[ch];
        ((uint4*)(sBlo + n * AST))[ch] = ((const uint4*)(g_wB_lo + n * 192))[ch];
    }
    for (int i = tid; i < 64 * 8; i += 256) {
        const int n = i >> 3, ch = i & 7;
        ((uint4*)(sG2hi + n * GST))[ch] = ((const uint4*)(g_g2_hi + n * 64))[ch];
        ((uint4*)(sG2lo + n * GST))[ch] = ((const uint4*)(g_g2_lo + n * 64))[ch];
    }
    if (tid < 64) { s_cb[tid] = conv_b[tid]; s_gb[tid] = gate_b[tid]; }
    __syncthreads();

    for (int p = blockIdx.x; p < NUM_TILES; p += gridDim.x) {
        const int t  = p >> 4;
        const int n0 = (p & 15) << 7;

        // ---- stage A tile: fp32 x -> bf16 hi/lo split, in registers ----
        for (int tap = 0; tap < 3; tap++) {
            const int tt = t + 2 * tap - 2;
            const bool ok = (tt >= 0 && tt < T_DIM);
            const float4* xs =
                (const float4*)(x + ((size_t)(ok ? tt : 0) * N_NODES + n0) * 64);
            for (int i = tid; i < 2048; i += 256) {        // 128 rows x 16 float4
                const int row = i >> 4, c4 = i & 15;
                float4 v = make_float4(0.f, 0.f, 0.f, 0.f);
                if (ok) v = xs[row * 16 + c4];
                const __nv_bfloat16 h0 = __float2bfloat16(v.x);
                const __nv_bfloat16 h1 = __float2bfloat16(v.y);
                const __nv_bfloat16 h2 = __float2bfloat16(v.z);
                const __nv_bfloat16 h3 = __float2bfloat16(v.w);
                const __nv_bfloat16 l0 = __float2bfloat16(v.x - __bfloat162float(h0));
                const __nv_bfloat16 l1 = __float2bfloat16(v.y - __bfloat162float(h1));
                const __nv_bfloat16 l2 = __float2bfloat16(v.z - __bfloat162float(h2));
                const __nv_bfloat16 l3 = __float2bfloat16(v.w - __bfloat162float(h3));
                const int off = row * AST + tap * 64 + c4 * 4;
                *(uint2*)(sAhi + off) = make_uint2(pack2(h0, h1), pack2(h2, h3));
                *(uint2*)(sAlo + off) = make_uint2(pack2(l0, l1), pack2(l2, l3));
            }
        }
        __syncthreads();

        // ---- MMA1: D1[128,128] = A[128,192].B^T, frag-reuse across combos ---
        float acc[2][8][4];
#pragma unroll
        for (int mb = 0; mb < 2; mb++)
#pragma unroll
            for (int j = 0; j < 8; j++)
#pragma unroll
                for (int r = 0; r < 4; r++) acc[mb][j][r] = 0.0f;

        for (int ks = 0; ks < 12; ks++) {
            const int k0 = ks * 16 + cp;
            uint32_t ah[2][4], al[2][4];
#pragma unroll
            for (int mb = 0; mb < 2; mb++) {
                const __nv_bfloat16* aph = sAhi + (rbase + mb * 16) * AST + k0;
                const __nv_bfloat16* apl = sAlo + (rbase + mb * 16) * AST + k0;
                ah[mb][0] = *(const uint32_t*)aph;
                ah[mb][1] = *(const uint32_t*)(aph + 8 * AST);
                ah[mb][2] = *(const uint32_t*)(aph + 8);
                ah[mb][3] = *(const uint32_t*)(aph + 8 * AST + 8);
                al[mb][0] = *(const uint32_t*)apl;
                al[mb][1] = *(const uint32_t*)(apl + 8 * AST);
                al[mb][2] = *(const uint32_t*)(apl + 8);
                al[mb][3] = *(const uint32_t*)(apl + 8 * AST + 8);
            }
#pragma unroll
            for (int jj = 0; jj < 8; jj++) {
                const int nbg = (jj < 4) ? (wn * 4 + jj) : (8 + wn * 4 + jj - 4);
                const __nv_bfloat16* bph = sBhi + (nbg * 8 + qid) * AST + k0;
                const __nv_bfloat16* bpl = sBlo + (nbg * 8 + qid) * AST + k0;
                uint32_t bh[2], bl[2];
                bh[0] = *(const uint32_t*)bph;
                bh[1] = *(const uint32_t*)(bph + 8);
                bl[0] = *(const uint32_t*)bpl;
                bl[1] = *(const uint32_t*)(bpl + 8);
                mma_bf16(acc[0][jj], ah[0], bh);
                mma_bf16(acc[1][jj], ah[1], bh);
                mma_bf16(acc[0][jj], ah[0], bl);
                mma_bf16(acc[1][jj], ah[1], bl);
                mma_bf16(acc[0][jj], al[0], bh);
                mma_bf16(acc[1][jj], al[1], bh);
            }
        }
        __syncthreads();   // all warps done reading A before h overwrites it

        // ---- epilogue1: h = (conv+cb)*sigmoid(gate+gb) -> bf16 hi/lo smem ---
#pragma unroll
        for (int mb = 0; mb < 2; mb++) {
#pragma unroll
            for (int jj = 0; jj < 4; jj++) {
                const float* ac = acc[mb][jj];
                const float* ag = acc[mb][jj + 4];
                const int c0 = wn * 32 + jj * 8 + cp;
                const int r0 = rbase + mb * 16;
                const float cb0 = s_cb[c0], cb1 = s_cb[c0 + 1];
                const float gb0 = s_gb[c0], gb1 = s_gb[c0 + 1];
                float h00 = (ac[0] + cb0) * (1.0f / (1.0f + __expf(-(ag[0] + gb0))));
                float h01 = (ac[1] + cb1) * (1.0f / (1.0f + __expf(-(ag[1] + gb1))));
                float h10 = (ac[2] + cb0) * (1.0f / (1.0f + __expf(-(ag[2] + gb0))));
                float h11 = (ac[3] + cb1) * (1.0f / (1.0f + __expf(-(ag[3] + gb1))));
                __nv_bfloat16 h00h = __float2bfloat16(h00);
                __nv_bfloat16 h01h = __float2bfloat16(h01);
                __nv_bfloat16 h10h = __float2bfloat16(h10);
                __nv_bfloat16 h11h = __float2bfloat16(h11);
                *(uint32_t*)(sAhi + r0 * AST + c0) = pack2(h00h, h01h);
                *(uint32_t*)(sAhi + (r0 + 8) * AST + c0) = pack2(h10h, h11h);
                *(uint32_t*)(sAlo + r0 * AST + c0) =
                    pack2(__float2bfloat16(h00 - __bfloat162float(h00h)),
                          __float2bfloat16(h01 - __bfloat162float(h01h)));
                *(uint32_t*)(sAlo + (r0 + 8) * AST + c0) =
                    pack2(__float2bfloat16(h10 - __bfloat162float(h10h)),
                          __float2bfloat16(h11 - __bfloat162float(h11h)));
            }
        }
        __syncthreads();

        // ---- MMA2: D2[128,64] = h[128,64] . g2^T ----
        float acc2[2][4][4];
#pragma unroll
        for (int mb = 0; mb < 2; mb++)
#pragma unroll
            for (int j = 0; j < 4; j++)
#pragma unroll
                for (int r = 0; r < 4; r++) acc2[mb][j][r] = 0.0f;

#pragma unroll
        for (int ks = 0; ks < 4; ks++) {
            const int k0 = ks * 16 + cp;
            uint32_t ah[2][4], al[2][4];
#pragma unroll
            for (int mb = 0; mb < 2; mb++) {
                const __nv_bfloat16* aph = sAhi + (rbase + mb * 16) * AST + k0;
                const __nv_bfloat16* apl = sAlo + (rbase + mb * 16) * AST + k0;
                ah[mb][0] = *(const uint32_t*)aph;
                ah[mb][1] = *(const uint32_t*)(aph + 8 * AST);
                ah[mb][2] = *(const uint32_t*)(aph + 8);
                ah[mb][3] = *(const uint32_t*)(aph + 8 * AST + 8);
                al[mb][0] = *(const uint32_t*)apl;
                al[mb][1] = *(const uint32_t*)(apl + 8 * AST);
                al[mb][2] = *(const uint32_t*)(apl + 8);
                al[mb][3] = *(const uint32_t*)(apl + 8 * AST + 8);
            }
#pragma unroll
            for (int jj = 0; jj < 4; jj++) {
                const __nv_bfloat16* bph = sG2hi + ((wn * 4 + jj) * 8 + qid) * GST + k0;
                const __nv_bfloat16* bpl = sG2lo + ((wn * 4 + jj) * 8 + qid) * GST + k0;
                uint32_t bh[2], bl[2];
                bh[0] = *(const uint32_t*)bph;
                bh[1] = *(const uint32_t*)(bph + 8);
                bl[0] = *(const uint32_t*)bpl;
                bl[1] = *(const uint32_t*)(bpl + 8);
                mma_bf16(acc2[0][jj], ah[0], bh);
                mma_bf16(acc2[1][jj], ah[1], bh);
                mma_bf16(acc2[0][jj], ah[0], bl);
                mma_bf16(acc2[1][jj], ah[1], bl);
                mma_bf16(acc2[0][jj], al[0], bh);
                mma_bf16(acc2[1][jj], al[1], bh);
            }
        }

        // ---- epilogue2: write xw tile ----
        float* obase = g_xw + ((size_t)t * N_NODES + n0) * 64;
#pragma unroll
        for (int mb = 0; mb < 2; mb++) {
#pragma unroll
            for (int jj = 0; jj < 4; jj++) {
                const int c0 = wn * 32 + jj * 8 + cp;
                const int r0 = rbase + mb * 16;
                *(float2*)(obase + r0 * 64 + c0) =
                    make_float2(acc2[mb][jj][0], acc2[mb][jj][1]);
                *(float2*)(obase + (r0 + 8) * 64 + c0) =
                    make_float2(acc2[mb][jj][2], acc2[mb][jj][3]);
            }
        }
        __syncthreads();   // protect sA reuse next iteration
    }
}

// ---------------- per-dst gather (float2 lanes, 2x edge unroll) -------------
__global__ void k_gather(float* __restrict__ out, const float* __restrict__ gcn_b) {
    __shared__ double ssum[C_DIM], ssq[C_DIM];
    const int tid = threadIdx.x;
    if (tid < C_DIM) { ssum[tid] = 0.0; ssq[tid] = 0.0; }
    __syncthreads();

    const int lane = tid & 31;
    const int warp = tid >> 5;
    const int wg   = blockIdx.x * 8 + warp;

    const float2 bias = ((const float2*)gcn_b)[lane];
    double ls0 = 0.0, ls1 = 0.0, lq0 = 0.0, lq1 = 0.0;

    for (int i = 0; i < 8; i++) {
        const int p = wg * 8 + i;
        const int t = p >> 11;
        const int n = p & 2047;
        const float2 v = ((const float2*)(g_xw + (size_t)p * 64))[lane];
        const float inv = g_invdeg[n];
        float a0 = fmaf(v.x, inv, bias.x);
        float a1 = fmaf(v.y, inv, bias.y);
        const float2* tb = (const float2*)(g_xw + (size_t)t * N_NODES * 64);
        int j = g_start[n];
        const int e1 = g_start[n + 1];
        for (; j + 1 < e1; j += 2) {
            const int   s0 = g_csr_src[j];
            const int   s1 = g_csr_src[j + 1];
            const float m0 = g_csr_norm[j];
            const float m1 = g_csr_norm[j + 1];
            const float2 w0 = tb[s0 * 32 + lane];
            const float2 w1 = tb[s1 * 32 + lane];
            a0 = fmaf(m0, w0.x, a0); a1 = fmaf(m0, w0.y, a1);
            a0 = fmaf(m1, w1.x, a0); a1 = fmaf(m1, w1.y, a1);
        }
        if (j < e1) {
            const int   s0 = g_csr_src[j];
            const float m0 = g_csr_norm[j];
            const float2 w0 = tb[s0 * 32 + lane];
            a0 = fmaf(m0, w0.x, a0); a1 = fmaf(m0, w0.y, a1);
        }
        ((float2*)(out + (size_t)p * 64))[lane] = make_float2(a0, a1);
        ls0 += a0; lq0 += (double)a0 * a0;
        ls1 += a1; lq1 += (double)a1 * a1;
    }
    atomicAdd(&ssum[2 * lane],     ls0); atomicAdd(&ssq[2 * lane],     lq0);
    atomicAdd(&ssum[2 * lane + 1], ls1); atomicAdd(&ssq[2 * lane + 1], lq1);
    __syncthreads();
    if (tid < C_DIM) {
        atomicAdd(&g_sum[tid],   ssum[tid]);
        atomicAdd(&g_sumsq[tid], ssq[tid]);
    }
}

__global__ void k_stats(const float* __restrict__ gamma, const float* __restrict__ beta) {
    int c = threadIdx.x;
    if (c < C_DIM) {
        const double M = (double)T_DIM * N_NODES;
        double m   = g_sum[c] / M;
        double var = g_sumsq[c] / M - m * m;
        float sc = (float)(1.0 / sqrt(var + 1e-5)) * gamma[c];
        g_scale[c] = sc;
        g_shift[c] = beta[c] - (float)m * sc;
    }
}

__global__ void k_apply(float* __restrict__ out) {
    const int idx = blockIdx.x * blockDim.x + threadIdx.x;
    const int c4  = idx & 15;
    float4 v  = reinterpret_cast<float4*>(out)[idx];
    const float4 sc = reinterpret_cast<const float4*>(g_scale)[c4];
    const float4 sh = reinterpret_cast<const float4*>(g_shift)[c4];
    v.x = fmaxf(fmaf(v.x, sc.x, sh.x), 0.0f);
    v.y = fmaxf(fmaf(v.y, sc.y, sh.y), 0.0f);
    v.z = fmaxf(fmaf(v.z, sc.z, sh.z), 0.0f);
    v.w = fmaxf(fmaf(v.w, sc.w, sh.w), 0.0f);
    reinterpret_cast<float4*>(out)[idx] = v;
}

// ---------------- launch ----------------
extern "C" void kernel_launch(void* const* d_in, const int* in_sizes, int n_in,
                              void* d_out, int out_size) {
    const float* x      = (const float*)d_in[0];
    const int*   ei     = (const int*)  d_in[1];
    const float* ew     = (const float*)d_in[2];
    const float* conv_w = (const float*)d_in[3];
    const float* conv_b = (const float*)d_in[4];
    const float* gate_w = (const float*)d_in[5];
    const float* gate_b = (const float*)d_in[6];
    const float* gcn_w  = (const float*)d_in[7];
    const float* gcn_b  = (const float*)d_in[8];
    const float* bn_g   = (const float*)d_in[9];
    const float* bn_b   = (const float*)d_in[10];
    float* out = (float*)d_out;

    // order chosen so ncu (-s 5 -c 1) captures k_mma as the 6th launch
    k_zero  <<<8, 256>>>();                              // 1
    k_deg   <<<E_EDGES / 256, 256>>>(ei, ew);            // 2
    k_scan  <<<1, 1024>>>();                             // 3
    k_fill  <<<E_EDGES / 256, 256>>>(ei, ew);            // 4
    k_prep_w<<<96, 256>>>(conv_w, gate_w, gcn_w);        // 5

    cudaFuncSetAttribute(k_mma, cudaFuncAttributeMaxDynamicSharedMemorySize,
                         SMEM_NEED);
    k_mma<<<148, 256, SMEM_NEED>>>(x, conv_b, gate_b);   // 6

    k_gather<<<(T_DIM * N_NODES) / (8 * 8), 256>>>(out, gcn_b);
    k_stats <<<1, 64>>>(bn_g, bn_b);
    k_apply <<<(T_DIM * N_NODES * C_DIM) / 4 / 256, 256>>>(out);
}